// round 13
// baseline (speedup 1.0000x reference)
#include <cuda_runtime.h>

// Problem constants: x [2, 64, 64, 96, 96]; NSEQ = bs*c = 128; T = d = 64; HID = 4
#define NSEQ 128
#define TSTEPS 64
#define ROWVEC 2304          // 96*96/4
#define VECS_PER_BC 147456   // 64*96*96/4

__device__ float g_mean[NSEQ * TSTEPS];            // [seq=b*64+c][t=d]
__device__ __align__(16) float g_last[NSEQ * 8];   // [seq][fwd h(4) | bwd h(4)]
__device__ float g_scale[NSEQ];                    // sigmoid output per (b,c)
__device__ unsigned g_ctr;                         // last-block counter

__device__ __forceinline__ void gdc_wait() {
    asm volatile("griddepcontrol.wait;" ::: "memory");
}
__device__ __forceinline__ void gdc_launch() {
    asm volatile("griddepcontrol.launch_dependents;" ::: "memory");
}

__device__ __forceinline__ float tanh_ap(float x) {
    float y;
    asm("tanh.approx.f32 %0, %1;" : "=f"(y) : "f"(x));
    return y;
}
__device__ __forceinline__ float sig_ap(float x) {
    return fmaf(0.5f, tanh_ap(0.5f * x), 0.5f);
}
__device__ __forceinline__ float sig_acc(float x) {
    return __fdividef(1.f, 1.f + __expf(-x));
}

// ---------------------------------------------------------------------------
// Kernel 1: mean over H,W per (b,c,d) row. Triggers dependent launch EARLY so
// the lstm kernel can preload its weights while the means stream.
// ---------------------------------------------------------------------------
__global__ void mean_kernel(const float* __restrict__ x) {
    if (threadIdx.x == 0) gdc_launch();
    int r = blockIdx.x;
    const float4* p = reinterpret_cast<const float4*>(x) + (size_t)r * ROWVEC;
    float4 v[9];
#pragma unroll
    for (int i = 0; i < 9; ++i) v[i] = p[threadIdx.x + i * 256];
    float s = 0.f;
#pragma unroll
    for (int i = 0; i < 9; ++i) s += (v[i].x + v[i].y) + (v[i].z + v[i].w);
#pragma unroll
    for (int off = 16; off > 0; off >>= 1)
        s += __shfl_down_sync(0xffffffffu, s, off);
    __shared__ float red[8];
    int warp = threadIdx.x >> 5, lane = threadIdx.x & 31;
    if (lane == 0) red[warp] = s;
    __syncthreads();
    if (threadIdx.x < 8) {
        s = red[threadIdx.x];
        s += __shfl_down_sync(0xffu, s, 4);
        s += __shfl_down_sync(0xffu, s, 2);
        s += __shfl_down_sync(0xffu, s, 1);
        if (threadIdx.x == 0) g_mean[r] = s * (1.f / 9216.f);
    }
}

// ---------------------------------------------------------------------------
// Kernel 2: 2-layer biLSTM (hidden=4) + SE MLP. 32 blocks x 128 threads.
// PDL: triggers scale's launch at entry; preloads weights before gdc_wait.
// Layer-1 fwd input projections are precomputed in parallel by all 128
// threads into SMEM, lightening the serial recurrence.
// ---------------------------------------------------------------------------
__global__ void lstm_kernel(
    const float* __restrict__ wih0f, const float* __restrict__ whh0f,
    const float* __restrict__ bih0f, const float* __restrict__ bhh0f,
    const float* __restrict__ wih0b, const float* __restrict__ whh0b,
    const float* __restrict__ bih0b, const float* __restrict__ bhh0b,
    const float* __restrict__ wih1f, const float* __restrict__ whh1f,
    const float* __restrict__ bih1f, const float* __restrict__ bhh1f,
    const float* __restrict__ wih1b, const float* __restrict__ whh1b,
    const float* __restrict__ bih1b, const float* __restrict__ bhh1b,
    const float* __restrict__ w1,    const float* __restrict__ w2) {
    __shared__ float s_mean[256];                     // 4 seqs x 64 t
    __shared__ __align__(16) float s_h0[4][516];      // 4 x (64 t x 8) + pad
    __shared__ float s_wih1f[128];                    // 16 x 8
    __shared__ float s_b1f[16];
    __shared__ float xproj[4 * 1032];                 // [seq][t*16+k], pad-free banks
    __shared__ __align__(16) float z[1024];           // fc input [2 x 512]
    __shared__ float h1s[64];                         // fc hidden [2 x 32]
    __shared__ unsigned s_last;

    int tid = threadIdx.x;
    if (tid == 0) gdc_launch();   // let scale's first wave start prefetching

    int j   = tid & 3;
    int u   = tid >> 2;
    int sl  = u >> 1;
    int dir = u & 1;
    int j1  = tid & 3;

    // ---- weight preloads BEFORE gdc_wait (overlap mean_kernel) ----
    float w_ih0[4], w_hh0[16], b0[4];
    float w1h[16], b1[4];
    float w1i[32];                 // used by bwd threads (16..31) only
    if (tid < 32) {
        const float* WIH0 = dir ? wih0b : wih0f;
        const float* WHH0 = dir ? whh0b : whh0f;
        const float* BI0  = dir ? bih0b : bih0f;
        const float* BH0  = dir ? bhh0b : bhh0f;
#pragma unroll
        for (int g = 0; g < 4; ++g) {
            int k = g * 4 + j;
            w_ih0[g] = WIH0[k];
            b0[g]    = BI0[k] + BH0[k];
#pragma unroll
            for (int m = 0; m < 4; ++m) w_hh0[g * 4 + m] = WHH0[k * 4 + m];
        }
        const float* WHH1 = (tid < 16) ? whh1f : whh1b;
#pragma unroll
        for (int g = 0; g < 4; ++g) {
            int k = g * 4 + j1;
#pragma unroll
            for (int m = 0; m < 4; ++m) w1h[g * 4 + m] = WHH1[k * 4 + m];
        }
        if (tid >= 16) {
            // bwd: direct projection weights + bias
#pragma unroll
            for (int g = 0; g < 4; ++g) {
                int k = g * 4 + j1;
                b1[g] = bih1b[k] + bhh1b[k];
#pragma unroll
                for (int m = 0; m < 8; ++m) w1i[g * 8 + m] = wih1b[k * 8 + m];
            }
        }
    } else if (tid < 64) {
        int lt = tid - 32;
#pragma unroll
        for (int i = 0; i < 4; ++i) s_wih1f[lt + i * 32] = wih1f[lt + i * 32];
        if (lt < 16) s_b1f[lt] = bih1f[lt] + bhh1f[lt];
    }

    // ---- wait for mean_kernel completion, then stage means ----
    gdc_wait();
    if (tid < 32) {
#pragma unroll
        for (int i = 0; i < 8; ++i)
            s_mean[tid + i * 32] = g_mean[blockIdx.x * 256 + tid + i * 32];
    }
    __syncthreads();

    // ---------------- layer 0 (warp 0 only) ----------------
    if (tid < 32) {
        float hj = 0.f, cj = 0.f;
        const float* mrow = s_mean + sl * 64;
        float* hrow = s_h0[sl];
        int foff = dir * 4 + j;
        for (int st = 0; st < TSTEPS; ++st) {
            int t = dir ? (TSTEPS - 1 - st) : st;
            float xt = mrow[t];
            float h0 = __shfl_sync(0xffffffffu, hj, 0, 4);
            float h1 = __shfl_sync(0xffffffffu, hj, 1, 4);
            float h2 = __shfl_sync(0xffffffffu, hj, 2, 4);
            float h3 = __shfl_sync(0xffffffffu, hj, 3, 4);
            float ga[4];
#pragma unroll
            for (int g = 0; g < 4; ++g) {
                float p0 = fmaf(w_ih0[g], xt, b0[g]);
                p0 = fmaf(w_hh0[g * 4 + 0], h0, p0);
                float p1 = fmaf(w_hh0[g * 4 + 2], h2, w_hh0[g * 4 + 1] * h1);
                float p2 = w_hh0[g * 4 + 3] * h3;
                ga[g] = p0 + (p1 + p2);
            }
            float ig = sig_ap(ga[0]), fg = sig_ap(ga[1]);
            float gg = tanh_ap(ga[2]), og = sig_ap(ga[3]);
            cj = fmaf(fg, cj, ig * gg);
            hj = og * tanh_ap(cj);
            hrow[t * 8 + foff] = hj;
        }
    }
    __syncthreads();

    // ---------------- layer-1 fwd input projections (all 128 threads) ------
    // xproj[s1][t][k] = b1f[k] + Wih1f[k,:] . h0[s1][t][:]
#pragma unroll
    for (int i = 0; i < 32; ++i) {
        int idx = tid + i * 128;          // 0..4095
        int s1 = idx >> 10;
        int rem = idx & 1023;
        int t = rem >> 4;
        int k = rem & 15;
        const float* wr = s_wih1f + k * 8;
        const float* hh = s_h0[s1] + t * 8;
        float a = s_b1f[k];
        a = fmaf(wr[0], hh[0], a);
        a = fmaf(wr[1], hh[1], a);
        a = fmaf(wr[2], hh[2], a);
        a = fmaf(wr[3], hh[3], a);
        a = fmaf(wr[4], hh[4], a);
        a = fmaf(wr[5], hh[5], a);
        a = fmaf(wr[6], hh[6], a);
        a = fmaf(wr[7], hh[7], a);
        xproj[s1 * 1032 + t * 16 + k] = a;
    }
    __syncthreads();

    // ---------------- layer 1 ----------------
    if (tid < 16) {
        int s1 = tid >> 2;
        const float* xp = xproj + s1 * 1032;
        float hj = 0.f, cj = 0.f;
        for (int t = 0; t < TSTEPS; ++t) {
            float h0 = __shfl_sync(0x0000ffffu, hj, 0, 4);
            float h1 = __shfl_sync(0x0000ffffu, hj, 1, 4);
            float h2 = __shfl_sync(0x0000ffffu, hj, 2, 4);
            float h3 = __shfl_sync(0x0000ffffu, hj, 3, 4);
            const float* xt = xp + t * 16;
            float ga[4];
#pragma unroll
            for (int g = 0; g < 4; ++g) {
                const float* wh = w1h + g * 4;
                float p0 = fmaf(wh[0], h0, xt[g * 4 + j1]);
                p0 = fmaf(wh[1], h1, p0);
                float p1 = fmaf(wh[3], h3, wh[2] * h2);
                ga[g] = p0 + p1;
            }
            float ig = sig_ap(ga[0]), fg = sig_ap(ga[1]);
            float gg = tanh_ap(ga[2]), og = sig_ap(ga[3]);
            cj = fmaf(fg, cj, ig * gg);
            hj = og * tanh_ap(cj);
        }
        g_last[(blockIdx.x * 4 + s1) * 8 + j1] = hj;
    } else if (tid < 32) {
        // backward: only the first processed step (original t=T-1) is used
        int s1 = (tid - 16) >> 2;
        const float* hrow = s_h0[s1];
        float4 xa = *reinterpret_cast<const float4*>(hrow + (TSTEPS - 1) * 8);
        float4 xb = *reinterpret_cast<const float4*>(hrow + (TSTEPS - 1) * 8 + 4);
        float ga[4];
#pragma unroll
        for (int g = 0; g < 4; ++g) {
            const float* wi = w1i + g * 8;
            float p0 = fmaf(wi[0], xa.x, b1[g]);
            p0 = fmaf(wi[1], xa.y, p0);
            float p1 = fmaf(wi[3], xa.w, wi[2] * xa.z);
            float p2 = fmaf(wi[5], xb.y, wi[4] * xb.x);
            float p3 = fmaf(wi[7], xb.w, wi[6] * xb.z);
            ga[g] = (p0 + p1) + (p2 + p3);
        }
        float cj = sig_ap(ga[0]) * tanh_ap(ga[2]);
        float hj = sig_ap(ga[3]) * tanh_ap(cj);
        g_last[(blockIdx.x * 4 + s1) * 8 + 4 + j1] = hj;
    }

    // ---------------- fc (SE MLP), last-arriving block, ALL 4 warps ---------
    __syncthreads();
    if (tid == 0) {
        __threadfence();
        s_last = (atomicAdd(&g_ctr, 1u) == 31u) ? 1u : 0u;
    }
    __syncthreads();
    if (!s_last) return;
    __threadfence();  // acquire: other blocks' g_last stores

    {
        float4* z4 = reinterpret_cast<float4*>(z);
        const float4* gl4 = reinterpret_cast<const float4*>(g_last);
        z4[tid] = gl4[tid];
        z4[tid + 128] = gl4[tid + 128];
    }
    __syncthreads();

    // h1 = relu(z @ w1.T): warp w handles rows 8w..8w+7, batched.
    {
        int w = tid >> 5, lane = tid & 31;
        float acc0[8], acc1[8];
#pragma unroll
        for (int r = 0; r < 8; ++r) { acc0[r] = 0.f; acc1[r] = 0.f; }
        const float* wbase = w1 + (w * 8) * 512;
#pragma unroll
        for (int cch = 0; cch < 16; ++cch) {
            int k = cch * 32 + lane;
            float zz0 = z[k], zz1 = z[512 + k];
#pragma unroll
            for (int r = 0; r < 8; ++r) {
                float wv = wbase[r * 512 + k];
                acc0[r] = fmaf(wv, zz0, acc0[r]);
                acc1[r] = fmaf(wv, zz1, acc1[r]);
            }
        }
#pragma unroll
        for (int r = 0; r < 8; ++r) {
#pragma unroll
            for (int off = 16; off > 0; off >>= 1) {
                acc0[r] += __shfl_down_sync(0xffffffffu, acc0[r], off);
                acc1[r] += __shfl_down_sync(0xffffffffu, acc1[r], off);
            }
            if (lane == 0) {
                h1s[w * 8 + r]      = fmaxf(acc0[r], 0.f);
                h1s[32 + w * 8 + r] = fmaxf(acc1[r], 0.f);
            }
        }
    }
    __syncthreads();

    // scale = sigmoid(h1 @ w2.T)
    if (tid < 64) {
        const float* wr = w2 + tid * 32;
        float a0 = 0.f, a1 = 0.f;
#pragma unroll
        for (int m = 0; m < 32; ++m) {
            float wv = wr[m];
            a0 = fmaf(wv, h1s[m], a0);
            a1 = fmaf(wv, h1s[32 + m], a1);
        }
        g_scale[tid]      = sig_acc(a0);
        g_scale[64 + tid] = sig_acc(a1);
    }
    if (tid == 0) g_ctr = 0;  // reset for next graph replay
}

// ---------------------------------------------------------------------------
// Kernel 3: out = x * scale[bc]. PDL: issues its x load before gdc_wait so
// the first wave's reads stream during the lstm's serial window.
// ---------------------------------------------------------------------------
__global__ void scale_kernel(const float* __restrict__ x,
                             float* __restrict__ out) {
    unsigned v = blockIdx.x * 256u + threadIdx.x;  // < 18,874,368
    float4 t = reinterpret_cast<const float4*>(x)[v];

    gdc_wait();  // lstm complete -> g_scale valid

    unsigned bc = v / VECS_PER_BC;                 // 0..127
    float sc = g_scale[bc];
    t.x *= sc; t.y *= sc; t.z *= sc; t.w *= sc;
    __stcs(reinterpret_cast<float4*>(out) + v, t);
}

// ---------------------------------------------------------------------------
extern "C" void kernel_launch(void* const* d_in, const int* in_sizes, int n_in,
                              void* d_out, int out_size) {
    const float* x = (const float*)d_in[0];

    mean_kernel<<<8192, 256>>>(x);

    cudaLaunchAttribute attr[1];
    attr[0].id = cudaLaunchAttributeProgrammaticStreamSerialization;
    attr[0].val.programmaticStreamSerializationAllowed = 1;

    {
        cudaLaunchConfig_t cfg = {};
        cfg.gridDim = dim3(32, 1, 1);
        cfg.blockDim = dim3(128, 1, 1);
        cfg.attrs = attr;
        cfg.numAttrs = 1;
        cudaLaunchKernelEx(&cfg, lstm_kernel,
            (const float*)d_in[1],  (const float*)d_in[2],
            (const float*)d_in[3],  (const float*)d_in[4],
            (const float*)d_in[5],  (const float*)d_in[6],
            (const float*)d_in[7],  (const float*)d_in[8],
            (const float*)d_in[9],  (const float*)d_in[10],
            (const float*)d_in[11], (const float*)d_in[12],
            (const float*)d_in[13], (const float*)d_in[14],
            (const float*)d_in[15], (const float*)d_in[16],
            (const float*)d_in[17], (const float*)d_in[18]);
    }
    {
        cudaLaunchConfig_t cfg = {};
        cfg.gridDim = dim3(73728, 1, 1);
        cfg.blockDim = dim3(256, 1, 1);
        cfg.attrs = attr;
        cfg.numAttrs = 1;
        cudaLaunchKernelEx(&cfg, scale_kernel, x, (float*)d_out);
    }
}

// round 14
// speedup vs baseline: 1.0754x; 1.0754x over previous
#include <cuda_runtime.h>

// Problem constants: x [2, 64, 64, 96, 96]; NSEQ = bs*c = 128; T = d = 64; HID = 4
#define NSEQ 128
#define TSTEPS 64
#define ROWVEC 2304          // 96*96/4
#define VECS_PER_BC 147456   // 64*96*96/4

__device__ float g_mean[NSEQ * TSTEPS];            // [seq=b*64+c][t=d]
__device__ __align__(16) float g_last[NSEQ * 8];   // [seq][fwd h(4) | bwd h(4)]
__device__ float g_scale[NSEQ];                    // sigmoid output per (b,c)
__device__ unsigned g_ctr;                         // last-block counter

__device__ __forceinline__ void gdc_wait() {
    asm volatile("griddepcontrol.wait;" ::: "memory");
}
__device__ __forceinline__ void gdc_launch() {
    asm volatile("griddepcontrol.launch_dependents;" ::: "memory");
}

__device__ __forceinline__ float tanh_ap(float x) {
    float y;
    asm("tanh.approx.f32 %0, %1;" : "=f"(y) : "f"(x));
    return y;
}
__device__ __forceinline__ float sig_ap(float x) {
    return fmaf(0.5f, tanh_ap(0.5f * x), 0.5f);
}
__device__ __forceinline__ float sig_acc(float x) {
    return __fdividef(1.f, 1.f + __expf(-x));
}

// ---------------------------------------------------------------------------
// Kernel 1: mean over H,W per (b,c,d) row. One block per row. Streaming
// loads (__ldcs). PDL trigger AFTER the g_mean store (race-free).
// ---------------------------------------------------------------------------
__global__ void mean_kernel(const float* __restrict__ x) {
    int r = blockIdx.x;
    const float4* p = reinterpret_cast<const float4*>(x) + (size_t)r * ROWVEC;
    float4 v[9];
#pragma unroll
    for (int i = 0; i < 9; ++i) v[i] = __ldcs(p + threadIdx.x + i * 256);
    float s = 0.f;
#pragma unroll
    for (int i = 0; i < 9; ++i) s += (v[i].x + v[i].y) + (v[i].z + v[i].w);
#pragma unroll
    for (int off = 16; off > 0; off >>= 1)
        s += __shfl_down_sync(0xffffffffu, s, off);
    __shared__ float red[8];
    int warp = threadIdx.x >> 5, lane = threadIdx.x & 31;
    if (lane == 0) red[warp] = s;
    __syncthreads();
    if (threadIdx.x < 8) {
        s = red[threadIdx.x];
        s += __shfl_down_sync(0xffu, s, 4);
        s += __shfl_down_sync(0xffu, s, 2);
        s += __shfl_down_sync(0xffu, s, 1);
        if (threadIdx.x == 0) {
            g_mean[r] = s * (1.f / 9216.f);
            gdc_launch();   // safe: the store this kernel produces is done
        }
    }
}

// ---------------------------------------------------------------------------
// Kernel 2: 2-layer biLSTM (hidden=4), warp 0 runs the recurrence; the
// last-arriving block runs the SE MLP with all 4 warps (R12 structure).
// PDL: weight preloads BEFORE gdc_wait (they don't depend on mean output);
// gdc_launch issued only AFTER each block's g_last / g_scale stores.
// ---------------------------------------------------------------------------
__global__ void lstm_kernel(
    const float* __restrict__ wih0f, const float* __restrict__ whh0f,
    const float* __restrict__ bih0f, const float* __restrict__ bhh0f,
    const float* __restrict__ wih0b, const float* __restrict__ whh0b,
    const float* __restrict__ bih0b, const float* __restrict__ bhh0b,
    const float* __restrict__ wih1f, const float* __restrict__ whh1f,
    const float* __restrict__ bih1f, const float* __restrict__ bhh1f,
    const float* __restrict__ wih1b, const float* __restrict__ whh1b,
    const float* __restrict__ bih1b, const float* __restrict__ bhh1b,
    const float* __restrict__ w1,    const float* __restrict__ w2) {
    __shared__ float s_mean[256];                     // 4 seqs x 64 t
    __shared__ __align__(16) float s_h0[4][516];      // 4 x (64 t x 8) + pad
    __shared__ __align__(16) float z[1024];           // fc input [2 x 512]
    __shared__ float h1s[64];                         // fc hidden [2 x 32]
    __shared__ unsigned s_last;

    int tid = threadIdx.x;

    // ---- weight preloads (independent of mean output) ----
    int j   = tid & 3;
    int u   = tid >> 2;
    int sl  = u >> 1;
    int dir = u & 1;
    int j1  = tid & 3;
    float w_ih0[4], w_hh0[16], b0[4];
    float w1i[32], w1h[16], b1[4];
    if (tid < 32) {
        const float* WIH0 = dir ? wih0b : wih0f;
        const float* WHH0 = dir ? whh0b : whh0f;
        const float* BI0  = dir ? bih0b : bih0f;
        const float* BH0  = dir ? bhh0b : bhh0f;
#pragma unroll
        for (int g = 0; g < 4; ++g) {
            int k = g * 4 + j;
            w_ih0[g] = WIH0[k];
            b0[g]    = BI0[k] + BH0[k];
#pragma unroll
            for (int m = 0; m < 4; ++m) w_hh0[g * 4 + m] = WHH0[k * 4 + m];
        }
        const float* WIH1 = (tid < 16) ? wih1f : wih1b;
        const float* WHH1 = (tid < 16) ? whh1f : whh1b;
        const float* BI1  = (tid < 16) ? bih1f : bih1b;
        const float* BH1  = (tid < 16) ? bhh1f : bhh1b;
#pragma unroll
        for (int g = 0; g < 4; ++g) {
            int k = g * 4 + j1;
            b1[g] = BI1[k] + BH1[k];
#pragma unroll
            for (int m = 0; m < 8; ++m) w1i[g * 8 + m] = WIH1[k * 8 + m];
#pragma unroll
            for (int m = 0; m < 4; ++m) w1h[g * 4 + m] = WHH1[k * 4 + m];
        }
    }

    // ---- wait for mean_kernel's trigger, then consume g_mean ----
    gdc_wait();

    if (tid < 32) {
#pragma unroll
        for (int i = 0; i < 8; ++i)
            s_mean[tid + i * 32] = g_mean[blockIdx.x * 256 + tid + i * 32];
        __syncwarp();

        // ---------------- layer 0 ----------------
        {
            float hj = 0.f, cj = 0.f;
            const float* mrow = s_mean + sl * 64;
            float* hrow = s_h0[sl];
            int foff = dir * 4 + j;
            for (int st = 0; st < TSTEPS; ++st) {
                int t = dir ? (TSTEPS - 1 - st) : st;
                float xt = mrow[t];
                float h0 = __shfl_sync(0xffffffffu, hj, 0, 4);
                float h1 = __shfl_sync(0xffffffffu, hj, 1, 4);
                float h2 = __shfl_sync(0xffffffffu, hj, 2, 4);
                float h3 = __shfl_sync(0xffffffffu, hj, 3, 4);
                float ga[4];
#pragma unroll
                for (int g = 0; g < 4; ++g) {
                    float p0 = fmaf(w_ih0[g], xt, b0[g]);
                    p0 = fmaf(w_hh0[g * 4 + 0], h0, p0);
                    float p1 = fmaf(w_hh0[g * 4 + 2], h2, w_hh0[g * 4 + 1] * h1);
                    float p2 = w_hh0[g * 4 + 3] * h3;
                    ga[g] = p0 + (p1 + p2);
                }
                float ig = sig_ap(ga[0]), fg = sig_ap(ga[1]);
                float gg = tanh_ap(ga[2]), og = sig_ap(ga[3]);
                cj = fmaf(fg, cj, ig * gg);
                hj = og * tanh_ap(cj);
                hrow[t * 8 + foff] = hj;
            }
        }
        __syncwarp();

        // ---------------- layer 1 ----------------
        if (tid < 16) {
            int s1 = tid >> 2;
            const float* hrow = s_h0[s1];
            float hj = 0.f, cj = 0.f;
            for (int t = 0; t < TSTEPS; ++t) {
                float4 xa = *reinterpret_cast<const float4*>(hrow + t * 8);
                float4 xb = *reinterpret_cast<const float4*>(hrow + t * 8 + 4);
                float h0 = __shfl_sync(0x0000ffffu, hj, 0, 4);
                float h1 = __shfl_sync(0x0000ffffu, hj, 1, 4);
                float h2 = __shfl_sync(0x0000ffffu, hj, 2, 4);
                float h3 = __shfl_sync(0x0000ffffu, hj, 3, 4);
                float ga[4];
#pragma unroll
                for (int g = 0; g < 4; ++g) {
                    const float* wi = w1i + g * 8;
                    const float* wh = w1h + g * 4;
                    float p0 = fmaf(wi[0], xa.x, b1[g]);
                    p0 = fmaf(wi[1], xa.y, p0);
                    float p1 = fmaf(wi[3], xa.w, wi[2] * xa.z);
                    float p2 = fmaf(wi[5], xb.y, wi[4] * xb.x);
                    float p3 = fmaf(wi[7], xb.w, wi[6] * xb.z);
                    float p4 = fmaf(wh[1], h1, wh[0] * h0);
                    float p5 = fmaf(wh[3], h3, wh[2] * h2);
                    ga[g] = ((p0 + p1) + (p2 + p3)) + (p4 + p5);
                }
                float ig = sig_ap(ga[0]), fg = sig_ap(ga[1]);
                float gg = tanh_ap(ga[2]), og = sig_ap(ga[3]);
                cj = fmaf(fg, cj, ig * gg);
                hj = og * tanh_ap(cj);
            }
            g_last[(blockIdx.x * 4 + s1) * 8 + j1] = hj;
        } else {
            // backward: only the first processed step (original t=T-1) is used
            int s1 = (tid - 16) >> 2;
            const float* hrow = s_h0[s1];
            float4 xa = *reinterpret_cast<const float4*>(hrow + (TSTEPS - 1) * 8);
            float4 xb = *reinterpret_cast<const float4*>(hrow + (TSTEPS - 1) * 8 + 4);
            float ga[4];
#pragma unroll
            for (int g = 0; g < 4; ++g) {
                const float* wi = w1i + g * 8;
                float p0 = fmaf(wi[0], xa.x, b1[g]);
                p0 = fmaf(wi[1], xa.y, p0);
                float p1 = fmaf(wi[3], xa.w, wi[2] * xa.z);
                float p2 = fmaf(wi[5], xb.y, wi[4] * xb.x);
                float p3 = fmaf(wi[7], xb.w, wi[6] * xb.z);
                ga[g] = (p0 + p1) + (p2 + p3);
            }
            float cj = sig_ap(ga[0]) * tanh_ap(ga[2]);
            float hj = sig_ap(ga[3]) * tanh_ap(cj);
            g_last[(blockIdx.x * 4 + s1) * 8 + 4 + j1] = hj;
        }
    }

    // ---------------- fc (SE MLP), last-arriving block, ALL 4 warps ---------
    __syncthreads();
    if (tid == 0) {
        __threadfence();
        s_last = (atomicAdd(&g_ctr, 1u) == 31u) ? 1u : 0u;
    }
    __syncthreads();
    if (!s_last) {
        // g_last stores for this block are complete and fenced -> safe trigger
        if (tid == 0) gdc_launch();
        return;
    }
    __threadfence();  // acquire: other blocks' g_last stores

    {
        float4* z4 = reinterpret_cast<float4*>(z);
        const float4* gl4 = reinterpret_cast<const float4*>(g_last);
        z4[tid] = gl4[tid];
        z4[tid + 128] = gl4[tid + 128];
    }
    __syncthreads();

    // h1 = relu(z @ w1.T): warp w handles rows 8w..8w+7, batched.
    {
        int w = tid >> 5, lane = tid & 31;
        float acc0[8], acc1[8];
#pragma unroll
        for (int r = 0; r < 8; ++r) { acc0[r] = 0.f; acc1[r] = 0.f; }
        const float* wbase = w1 + (w * 8) * 512;
#pragma unroll
        for (int cch = 0; cch < 16; ++cch) {
            int k = cch * 32 + lane;
            float zz0 = z[k], zz1 = z[512 + k];
#pragma unroll
            for (int r = 0; r < 8; ++r) {
                float wv = wbase[r * 512 + k];
                acc0[r] = fmaf(wv, zz0, acc0[r]);
                acc1[r] = fmaf(wv, zz1, acc1[r]);
            }
        }
#pragma unroll
        for (int r = 0; r < 8; ++r) {
#pragma unroll
            for (int off = 16; off > 0; off >>= 1) {
                acc0[r] += __shfl_down_sync(0xffffffffu, acc0[r], off);
                acc1[r] += __shfl_down_sync(0xffffffffu, acc1[r], off);
            }
            if (lane == 0) {
                h1s[w * 8 + r]      = fmaxf(acc0[r], 0.f);
                h1s[32 + w * 8 + r] = fmaxf(acc1[r], 0.f);
            }
        }
    }
    __syncthreads();

    // scale = sigmoid(h1 @ w2.T)
    if (tid < 64) {
        const float* wr = w2 + tid * 32;
        float a0 = 0.f, a1 = 0.f;
#pragma unroll
        for (int m = 0; m < 32; ++m) {
            float wv = wr[m];
            a0 = fmaf(wv, h1s[m], a0);
            a1 = fmaf(wv, h1s[32 + m], a1);
        }
        g_scale[tid]      = sig_acc(a0);
        g_scale[64 + tid] = sig_acc(a1);
    }
    __syncthreads();
    if (tid == 0) {
        g_ctr = 0;          // reset for next graph replay
        __threadfence();
        gdc_launch();       // g_scale fully written -> release scale_kernel
    }
}

// ---------------------------------------------------------------------------
// Kernel 3: out = x * scale[bc]. One float4 per thread, exact grid. PDL:
// the x load issues BEFORE gdc_wait so first-wave reads overlap the lstm tail.
// ---------------------------------------------------------------------------
__global__ void scale_kernel(const float* __restrict__ x,
                             float* __restrict__ out) {
    unsigned v = blockIdx.x * 256u + threadIdx.x;  // < 18,874,368
    float4 t = reinterpret_cast<const float4*>(x)[v];

    gdc_wait();  // lstm blocks all triggered after their stores -> g_scale valid

    unsigned bc = v / VECS_PER_BC;                 // 0..127
    float sc = g_scale[bc];
    t.x *= sc; t.y *= sc; t.z *= sc; t.w *= sc;
    __stcs(reinterpret_cast<float4*>(out) + v, t);
}

// ---------------------------------------------------------------------------
extern "C" void kernel_launch(void* const* d_in, const int* in_sizes, int n_in,
                              void* d_out, int out_size) {
    const float* x = (const float*)d_in[0];

    mean_kernel<<<8192, 256>>>(x);

    cudaLaunchAttribute attr[1];
    attr[0].id = cudaLaunchAttributeProgrammaticStreamSerialization;
    attr[0].val.programmaticStreamSerializationAllowed = 1;

    {
        cudaLaunchConfig_t cfg = {};
        cfg.gridDim = dim3(32, 1, 1);
        cfg.blockDim = dim3(128, 1, 1);
        cfg.attrs = attr;
        cfg.numAttrs = 1;
        cudaLaunchKernelEx(&cfg, lstm_kernel,
            (const float*)d_in[1],  (const float*)d_in[2],
            (const float*)d_in[3],  (const float*)d_in[4],
            (const float*)d_in[5],  (const float*)d_in[6],
            (const float*)d_in[7],  (const float*)d_in[8],
            (const float*)d_in[9],  (const float*)d_in[10],
            (const float*)d_in[11], (const float*)d_in[12],
            (const float*)d_in[13], (const float*)d_in[14],
            (const float*)d_in[15], (const float*)d_in[16],
            (const float*)d_in[17], (const float*)d_in[18]);
    }
    {
        cudaLaunchConfig_t cfg = {};
        cfg.gridDim = dim3(73728, 1, 1);
        cfg.blockDim = dim3(256, 1, 1);
        cfg.attrs = attr;
        cfg.numAttrs = 1;
        cudaLaunchKernelEx(&cfg, scale_kernel, x, (float*)d_out);
    }
}

// round 15
// speedup vs baseline: 1.0856x; 1.0096x over previous
#include <cuda_runtime.h>

// Problem constants: x [2, 64, 64, 96, 96]; NSEQ = bs*c = 128; T = d = 64; HID = 4
#define NSEQ 128
#define TSTEPS 64
#define ROWVEC 2304          // 96*96/4
#define VECS_PER_BC 147456   // 64*96*96/4

__device__ float g_mean[NSEQ * TSTEPS];            // [seq=b*64+c][t=d]
__device__ __align__(16) float g_last[NSEQ * 8];   // [seq][fwd h(4) | bwd h(4)]
__device__ float g_scale[NSEQ];                    // sigmoid output per (b,c)
__device__ unsigned g_ctr;                         // last-block counter
__device__ unsigned seq_done[NSEQ];                // per-seq mean-row arrivals

__device__ __forceinline__ void gdc_wait() {
    asm volatile("griddepcontrol.wait;" ::: "memory");
}
__device__ __forceinline__ void gdc_launch() {
    asm volatile("griddepcontrol.launch_dependents;" ::: "memory");
}

__device__ __forceinline__ float tanh_ap(float x) {
    float y;
    asm("tanh.approx.f32 %0, %1;" : "=f"(y) : "f"(x));
    return y;
}
__device__ __forceinline__ float sig_ap(float x) {
    return fmaf(0.5f, tanh_ap(0.5f * x), 0.5f);
}
__device__ __forceinline__ float sig_acc(float x) {
    return __fdividef(1.f, 1.f + __expf(-x));
}

// ---------------------------------------------------------------------------
// Kernel 1: mean over H,W per (b,c,d) row. gdc_launch AT ENTRY — PDL is only
// a co-scheduler here; data correctness is carried by seq_done counters
// (release: threadfence + atomicAdd after the g_mean store).
// ---------------------------------------------------------------------------
__global__ void mean_kernel(const float* __restrict__ x) {
    if (threadIdx.x == 0) gdc_launch();
    int r = blockIdx.x;
    const float4* p = reinterpret_cast<const float4*>(x) + (size_t)r * ROWVEC;
    float4 v[9];
#pragma unroll
    for (int i = 0; i < 9; ++i) v[i] = __ldcs(p + threadIdx.x + i * 256);
    float s = 0.f;
#pragma unroll
    for (int i = 0; i < 9; ++i) s += (v[i].x + v[i].y) + (v[i].z + v[i].w);
#pragma unroll
    for (int off = 16; off > 0; off >>= 1)
        s += __shfl_down_sync(0xffffffffu, s, off);
    __shared__ float red[8];
    int warp = threadIdx.x >> 5, lane = threadIdx.x & 31;
    if (lane == 0) red[warp] = s;
    __syncthreads();
    if (threadIdx.x < 8) {
        s = red[threadIdx.x];
        s += __shfl_down_sync(0xffu, s, 4);
        s += __shfl_down_sync(0xffu, s, 2);
        s += __shfl_down_sync(0xffu, s, 1);
        if (threadIdx.x == 0) {
            g_mean[r] = s * (1.f / 9216.f);
            __threadfence();
            atomicAdd(&seq_done[r >> 6], 1u);   // release this row
        }
    }
}

// ---------------------------------------------------------------------------
// Kernel 2: 2-layer biLSTM (hidden=4) + SE MLP. 32 blocks x 128 threads.
// Launched early via PDL; each block spins on its 4 per-seq counters so it
// starts as soon as ITS data is ready (overlapping mean's tail). The
// lstm->scale edge keeps R14's measured-good protocol (trigger after stores).
// ---------------------------------------------------------------------------
__global__ void lstm_kernel(
    const float* __restrict__ wih0f, const float* __restrict__ whh0f,
    const float* __restrict__ bih0f, const float* __restrict__ bhh0f,
    const float* __restrict__ wih0b, const float* __restrict__ whh0b,
    const float* __restrict__ bih0b, const float* __restrict__ bhh0b,
    const float* __restrict__ wih1f, const float* __restrict__ whh1f,
    const float* __restrict__ bih1f, const float* __restrict__ bhh1f,
    const float* __restrict__ wih1b, const float* __restrict__ whh1b,
    const float* __restrict__ bih1b, const float* __restrict__ bhh1b,
    const float* __restrict__ w1,    const float* __restrict__ w2) {
    __shared__ float s_mean[256];                     // 4 seqs x 64 t
    __shared__ __align__(16) float s_h0[4][516];      // 4 x (64 t x 8) + pad
    __shared__ __align__(16) float z[1024];           // fc input [2 x 512]
    __shared__ float h1s[64];                         // fc hidden [2 x 32]
    __shared__ unsigned s_last;

    int tid = threadIdx.x;
    int bid = blockIdx.x;

    // ---- weight preloads (independent of mean output) ----
    int j   = tid & 3;
    int u   = tid >> 2;
    int sl  = u >> 1;
    int dir = u & 1;
    int j1  = tid & 3;
    float w_ih0[4], w_hh0[16], b0[4];
    float w1i[32], w1h[16], b1[4];
    if (tid < 32) {
        const float* WIH0 = dir ? wih0b : wih0f;
        const float* WHH0 = dir ? whh0b : whh0f;
        const float* BI0  = dir ? bih0b : bih0f;
        const float* BH0  = dir ? bhh0b : bhh0f;
#pragma unroll
        for (int g = 0; g < 4; ++g) {
            int k = g * 4 + j;
            w_ih0[g] = WIH0[k];
            b0[g]    = BI0[k] + BH0[k];
#pragma unroll
            for (int m = 0; m < 4; ++m) w_hh0[g * 4 + m] = WHH0[k * 4 + m];
        }
        const float* WIH1 = (tid < 16) ? wih1f : wih1b;
        const float* WHH1 = (tid < 16) ? whh1f : whh1b;
        const float* BI1  = (tid < 16) ? bih1f : bih1b;
        const float* BH1  = (tid < 16) ? bhh1f : bhh1b;
#pragma unroll
        for (int g = 0; g < 4; ++g) {
            int k = g * 4 + j1;
            b1[g] = BI1[k] + BH1[k];
#pragma unroll
            for (int m = 0; m < 8; ++m) w1i[g * 8 + m] = WIH1[k * 8 + m];
#pragma unroll
            for (int m = 0; m < 4; ++m) w1h[g * 4 + m] = WHH1[k * 4 + m];
        }
    }

    // ---- wait for THIS block's 4 sequences via spin counters ----
    if (tid < 4) {
        volatile unsigned* sd = (volatile unsigned*)seq_done;
        while (sd[bid * 4 + tid] < 64u) __nanosleep(64);
    }
    __syncthreads();
    __threadfence();   // acquire the g_mean stores

    if (tid < 32) {
#pragma unroll
        for (int i = 0; i < 8; ++i)
            s_mean[tid + i * 32] = g_mean[bid * 256 + tid + i * 32];
        __syncwarp();
        // reset counters for graph replay (sole consumer, producers arrived)
        if (tid < 4) seq_done[bid * 4 + tid] = 0u;

        // ---------------- layer 0 ----------------
        {
            float hj = 0.f, cj = 0.f;
            const float* mrow = s_mean + sl * 64;
            float* hrow = s_h0[sl];
            int foff = dir * 4 + j;
            for (int st = 0; st < TSTEPS; ++st) {
                int t = dir ? (TSTEPS - 1 - st) : st;
                float xt = mrow[t];
                float h0 = __shfl_sync(0xffffffffu, hj, 0, 4);
                float h1 = __shfl_sync(0xffffffffu, hj, 1, 4);
                float h2 = __shfl_sync(0xffffffffu, hj, 2, 4);
                float h3 = __shfl_sync(0xffffffffu, hj, 3, 4);
                float ga[4];
#pragma unroll
                for (int g = 0; g < 4; ++g) {
                    float p0 = fmaf(w_ih0[g], xt, b0[g]);
                    p0 = fmaf(w_hh0[g * 4 + 0], h0, p0);
                    float p1 = fmaf(w_hh0[g * 4 + 2], h2, w_hh0[g * 4 + 1] * h1);
                    float p2 = w_hh0[g * 4 + 3] * h3;
                    ga[g] = p0 + (p1 + p2);
                }
                float ig = sig_ap(ga[0]), fg = sig_ap(ga[1]);
                float gg = tanh_ap(ga[2]), og = sig_ap(ga[3]);
                cj = fmaf(fg, cj, ig * gg);
                hj = og * tanh_ap(cj);
                hrow[t * 8 + foff] = hj;
            }
        }
        __syncwarp();

        // ---------------- layer 1 ----------------
        if (tid < 16) {
            int s1 = tid >> 2;
            const float* hrow = s_h0[s1];
            float hj = 0.f, cj = 0.f;
            for (int t = 0; t < TSTEPS; ++t) {
                float4 xa = *reinterpret_cast<const float4*>(hrow + t * 8);
                float4 xb = *reinterpret_cast<const float4*>(hrow + t * 8 + 4);
                float h0 = __shfl_sync(0x0000ffffu, hj, 0, 4);
                float h1 = __shfl_sync(0x0000ffffu, hj, 1, 4);
                float h2 = __shfl_sync(0x0000ffffu, hj, 2, 4);
                float h3 = __shfl_sync(0x0000ffffu, hj, 3, 4);
                float ga[4];
#pragma unroll
                for (int g = 0; g < 4; ++g) {
                    const float* wi = w1i + g * 8;
                    const float* wh = w1h + g * 4;
                    float p0 = fmaf(wi[0], xa.x, b1[g]);
                    p0 = fmaf(wi[1], xa.y, p0);
                    float p1 = fmaf(wi[3], xa.w, wi[2] * xa.z);
                    float p2 = fmaf(wi[5], xb.y, wi[4] * xb.x);
                    float p3 = fmaf(wi[7], xb.w, wi[6] * xb.z);
                    float p4 = fmaf(wh[1], h1, wh[0] * h0);
                    float p5 = fmaf(wh[3], h3, wh[2] * h2);
                    ga[g] = ((p0 + p1) + (p2 + p3)) + (p4 + p5);
                }
                float ig = sig_ap(ga[0]), fg = sig_ap(ga[1]);
                float gg = tanh_ap(ga[2]), og = sig_ap(ga[3]);
                cj = fmaf(fg, cj, ig * gg);
                hj = og * tanh_ap(cj);
            }
            g_last[(bid * 4 + s1) * 8 + j1] = hj;
        } else {
            // backward: only the first processed step (original t=T-1) is used
            int s1 = (tid - 16) >> 2;
            const float* hrow = s_h0[s1];
            float4 xa = *reinterpret_cast<const float4*>(hrow + (TSTEPS - 1) * 8);
            float4 xb = *reinterpret_cast<const float4*>(hrow + (TSTEPS - 1) * 8 + 4);
            float ga[4];
#pragma unroll
            for (int g = 0; g < 4; ++g) {
                const float* wi = w1i + g * 8;
                float p0 = fmaf(wi[0], xa.x, b1[g]);
                p0 = fmaf(wi[1], xa.y, p0);
                float p1 = fmaf(wi[3], xa.w, wi[2] * xa.z);
                float p2 = fmaf(wi[5], xb.y, wi[4] * xb.x);
                float p3 = fmaf(wi[7], xb.w, wi[6] * xb.z);
                ga[g] = (p0 + p1) + (p2 + p3);
            }
            float cj = sig_ap(ga[0]) * tanh_ap(ga[2]);
            float hj = sig_ap(ga[3]) * tanh_ap(cj);
            g_last[(bid * 4 + s1) * 8 + 4 + j1] = hj;
        }
    }

    // ---------------- fc (SE MLP), last-arriving block, ALL 4 warps ---------
    __syncthreads();
    if (tid == 0) {
        __threadfence();
        s_last = (atomicAdd(&g_ctr, 1u) == 31u) ? 1u : 0u;
    }
    __syncthreads();
    if (!s_last) {
        // this block's g_last stores are complete and fenced -> safe trigger
        if (tid == 0) gdc_launch();
        return;
    }
    __threadfence();  // acquire: other blocks' g_last stores

    {
        float4* z4 = reinterpret_cast<float4*>(z);
        const float4* gl4 = reinterpret_cast<const float4*>(g_last);
        z4[tid] = gl4[tid];
        z4[tid + 128] = gl4[tid + 128];
    }
    __syncthreads();

    // h1 = relu(z @ w1.T): warp w handles rows 8w..8w+7, batched.
    {
        int w = tid >> 5, lane = tid & 31;
        float acc0[8], acc1[8];
#pragma unroll
        for (int r = 0; r < 8; ++r) { acc0[r] = 0.f; acc1[r] = 0.f; }
        const float* wbase = w1 + (w * 8) * 512;
#pragma unroll
        for (int cch = 0; cch < 16; ++cch) {
            int k = cch * 32 + lane;
            float zz0 = z[k], zz1 = z[512 + k];
#pragma unroll
            for (int r = 0; r < 8; ++r) {
                float wv = wbase[r * 512 + k];
                acc0[r] = fmaf(wv, zz0, acc0[r]);
                acc1[r] = fmaf(wv, zz1, acc1[r]);
            }
        }
#pragma unroll
        for (int r = 0; r < 8; ++r) {
#pragma unroll
            for (int off = 16; off > 0; off >>= 1) {
                acc0[r] += __shfl_down_sync(0xffffffffu, acc0[r], off);
                acc1[r] += __shfl_down_sync(0xffffffffu, acc1[r], off);
            }
            if (lane == 0) {
                h1s[w * 8 + r]      = fmaxf(acc0[r], 0.f);
                h1s[32 + w * 8 + r] = fmaxf(acc1[r], 0.f);
            }
        }
    }
    __syncthreads();

    // scale = sigmoid(h1 @ w2.T)
    if (tid < 64) {
        const float* wr = w2 + tid * 32;
        float a0 = 0.f, a1 = 0.f;
#pragma unroll
        for (int m = 0; m < 32; ++m) {
            float wv = wr[m];
            a0 = fmaf(wv, h1s[m], a0);
            a1 = fmaf(wv, h1s[32 + m], a1);
        }
        g_scale[tid]      = sig_acc(a0);
        g_scale[64 + tid] = sig_acc(a1);
    }
    __syncthreads();
    if (tid == 0) {
        g_ctr = 0;          // reset for next graph replay
        __threadfence();
        gdc_launch();       // g_scale fully written -> release scale_kernel
    }
}

// ---------------------------------------------------------------------------
// Kernel 3: out = x * scale[bc]. One float4 per thread, exact grid. PDL:
// the x load issues BEFORE gdc_wait so first-wave reads overlap the lstm tail.
// ---------------------------------------------------------------------------
__global__ void scale_kernel(const float* __restrict__ x,
                             float* __restrict__ out) {
    unsigned v = blockIdx.x * 256u + threadIdx.x;  // < 18,874,368
    float4 t = reinterpret_cast<const float4*>(x)[v];

    gdc_wait();  // all lstm blocks triggered after their stores -> g_scale valid

    unsigned bc = v / VECS_PER_BC;                 // 0..127
    float sc = g_scale[bc];
    t.x *= sc; t.y *= sc; t.z *= sc; t.w *= sc;
    __stcs(reinterpret_cast<float4*>(out) + v, t);
}

// ---------------------------------------------------------------------------
extern "C" void kernel_launch(void* const* d_in, const int* in_sizes, int n_in,
                              void* d_out, int out_size) {
    const float* x = (const float*)d_in[0];

    mean_kernel<<<8192, 256>>>(x);

    cudaLaunchAttribute attr[1];
    attr[0].id = cudaLaunchAttributeProgrammaticStreamSerialization;
    attr[0].val.programmaticStreamSerializationAllowed = 1;

    {
        cudaLaunchConfig_t cfg = {};
        cfg.gridDim = dim3(32, 1, 1);
        cfg.blockDim = dim3(128, 1, 1);
        cfg.attrs = attr;
        cfg.numAttrs = 1;
        cudaLaunchKernelEx(&cfg, lstm_kernel,
            (const float*)d_in[1],  (const float*)d_in[2],
            (const float*)d_in[3],  (const float*)d_in[4],
            (const float*)d_in[5],  (const float*)d_in[6],
            (const float*)d_in[7],  (const float*)d_in[8],
            (const float*)d_in[9],  (const float*)d_in[10],
            (const float*)d_in[11], (const float*)d_in[12],
            (const float*)d_in[13], (const float*)d_in[14],
            (const float*)d_in[15], (const float*)d_in[16],
            (const float*)d_in[17], (const float*)d_in[18]);
    }
    {
        cudaLaunchConfig_t cfg = {};
        cfg.gridDim = dim3(73728, 1, 1);
        cfg.blockDim = dim3(256, 1, 1);
        cfg.attrs = attr;
        cfg.numAttrs = 1;
        cudaLaunchKernelEx(&cfg, scale_kernel, x, (float*)d_out);
    }
}